// round 4
// baseline (speedup 1.0000x reference)
#include <cuda_runtime.h>
#include <cstdint>

// TtLlamaRotary: out[n,s,:] = x[n,s,:] @ R[s,:,:]
//   xq  [8,128,128], xk [1,128,128], rot [128,128,128], out = concat (9,128,128)
//
// Grid (128 s, 2 d-halves); block 256 = 16 h-groups x 16 threads.
// Thread owns 4 output columns (float4 R loads), accumulates with packed
// fma.rn.f32x2 against x values staged in smem as duplicated float2.

#define SEQ_LEN 128
#define HEAD_DIM 128
#define NQ 8
#define NROWS 9
#define DTILE 64
#define TPG 16                        // threads per h-group (4 cols each)
#define NGROUPS 16
#define HCHUNK (HEAD_DIM / NGROUPS)   // 8
#define NTHREADS (NGROUPS * TPG)      // 256

__global__ __launch_bounds__(NTHREADS, 2)
void rotary_kernel(const float* __restrict__ xq,
                   const float* __restrict__ xk,
                   const float* __restrict__ rot,
                   float* __restrict__ out) {
    const int s   = blockIdx.x;
    const int dh  = blockIdx.y;          // d half: 0 or 1
    const int tid = threadIdx.x;
    const int g   = tid / TPG;           // h-group 0..15
    const int t   = tid % TPG;           // 4-col slot 0..15

    __shared__ float2 xs2[NROWS][HEAD_DIM];          // (x,x) duplicated
    __shared__ float  part[NGROUPS][NROWS][DTILE];

    // Stage x rows, pre-packed for f32x2 FMA.
    for (int idx = tid; idx < NROWS * HEAD_DIM; idx += NTHREADS) {
        const int n = idx >> 7;
        const int d = idx & 127;
        const float v = (n < NQ) ? xq[(n * SEQ_LEN + s) * HEAD_DIM + d]
                                 : xk[s * HEAD_DIM + d];
        xs2[n][d] = make_float2(v, v);
    }
    __syncthreads();

    // R as float4: element (h, dh*64 + 4t) -> R4[h*32], base offset below.
    const float4* __restrict__ R4 =
        (const float4*)rot + (size_t)s * (HEAD_DIM * HEAD_DIM / 4) + dh * (DTILE / 4) + t;

    unsigned long long acc01[NROWS], acc23[NROWS];
    #pragma unroll
    for (int n = 0; n < NROWS; n++) { acc01[n] = 0ull; acc23[n] = 0ull; }

    #pragma unroll
    for (int h = 0; h < HCHUNK; h++) {
        const int hh = g * HCHUNK + h;
        const float4 r = R4[(size_t)hh * (HEAD_DIM / 4)];
        unsigned long long r01, r23;
        asm("mov.b64 %0, {%1, %2};" : "=l"(r01) : "f"(r.x), "f"(r.y));
        asm("mov.b64 %0, {%1, %2};" : "=l"(r23) : "f"(r.z), "f"(r.w));
        #pragma unroll
        for (int n = 0; n < NROWS; n++) {
            const unsigned long long x2 =
                *(const unsigned long long*)&xs2[n][hh];   // LDS.64 broadcast
            asm("fma.rn.f32x2 %0, %1, %2, %0;" : "+l"(acc01[n]) : "l"(x2), "l"(r01));
            asm("fma.rn.f32x2 %0, %1, %2, %0;" : "+l"(acc23[n]) : "l"(x2), "l"(r23));
        }
    }

    // Unpack and write partials (STS.128).
    #pragma unroll
    for (int n = 0; n < NROWS; n++) {
        float a0, a1, a2, a3;
        asm("mov.b64 {%0, %1}, %2;" : "=f"(a0), "=f"(a1) : "l"(acc01[n]));
        asm("mov.b64 {%0, %1}, %2;" : "=f"(a2), "=f"(a3) : "l"(acc23[n]));
        *(float4*)&part[g][n][t * 4] = make_float4(a0, a1, a2, a3);
    }
    __syncthreads();

    // Reduce 16 partials: 9 rows x 16 float4-chunks = 144 outputs, 1/thread.
    // Note out row index works uniformly: n=8 lands exactly at the xk block.
    if (tid < NROWS * (DTILE / 4)) {
        const int n = tid / (DTILE / 4);
        const int c = tid % (DTILE / 4);
        float4 v = make_float4(0.f, 0.f, 0.f, 0.f);
        #pragma unroll
        for (int gg = 0; gg < NGROUPS; gg++) {
            const float4 p = *(const float4*)&part[gg][n][c * 4];
            v.x += p.x; v.y += p.y; v.z += p.z; v.w += p.w;
        }
        const size_t o = (size_t)(n * SEQ_LEN + s) * HEAD_DIM + dh * DTILE + c * 4;
        *(float4*)(out + o) = v;
    }
}

extern "C" void kernel_launch(void* const* d_in, const int* in_sizes, int n_in,
                              void* d_out, int out_size) {
    const float* xq  = (const float*)d_in[0];
    const float* xk  = (const float*)d_in[1];
    const float* rot = (const float*)d_in[2];
    float* out = (float*)d_out;

    dim3 grid(SEQ_LEN, 2);
    rotary_kernel<<<grid, NTHREADS>>>(xq, xk, rot, out);
}

// round 5
// speedup vs baseline: 1.3029x; 1.3029x over previous
#include <cuda_runtime.h>
#include <cstdint>

// TtLlamaRotary: out[n,s,:] = x[n,s,:] @ R[s,:,:]
//   xq  [8,128,128], xk [1,128,128], rot [128,128,128], out = concat (9,128,128)
//
// Grid (128 s, 2 d-halves); block 256 = 16 h-groups x 16 threads.
// Thread owns 4 output columns. R slice (8 x float4) is PREFETCHED into
// registers before the x-staging barrier so both DRAM round trips overlap.
// Accumulation uses packed fma.rn.f32x2 against x staged as duplicated float2.

#define SEQ_LEN 128
#define HEAD_DIM 128
#define NQ 8
#define NROWS 9
#define DTILE 64
#define TPG 16                        // threads per h-group (4 cols each)
#define NGROUPS 16
#define HCHUNK (HEAD_DIM / NGROUPS)   // 8
#define NTHREADS (NGROUPS * TPG)      // 256

__global__ __launch_bounds__(NTHREADS, 2)
void rotary_kernel(const float* __restrict__ xq,
                   const float* __restrict__ xk,
                   const float* __restrict__ rot,
                   float* __restrict__ out) {
    const int s   = blockIdx.x;
    const int dh  = blockIdx.y;          // d half: 0 or 1
    const int tid = threadIdx.x;
    const int g   = tid / TPG;           // h-group 0..15
    const int t   = tid % TPG;           // 4-col slot 0..15

    __shared__ float2 xs2[NROWS][HEAD_DIM];          // (x,x) duplicated
    __shared__ float  part[NGROUPS][NROWS][DTILE];

    // ---- Prefetch R slice into registers (independent of xs staging) ----
    const float4* __restrict__ R4 =
        (const float4*)rot + (size_t)s * (HEAD_DIM * HEAD_DIM / 4) + dh * (DTILE / 4) + t;
    float4 rv[HCHUNK];
    #pragma unroll
    for (int h = 0; h < HCHUNK; h++)
        rv[h] = R4[(size_t)(g * HCHUNK + h) * (HEAD_DIM / 4)];

    // ---- Stage x rows (float4 loads), pre-packed for f32x2 FMA ----
    // 9 rows x 32 float4 = 288 chunks over 256 threads.
    for (int idx = tid; idx < NROWS * (HEAD_DIM / 4); idx += NTHREADS) {
        const int n = idx >> 5;          // row 0..8
        const int c = idx & 31;          // float4 chunk within row
        const float4 v = (n < NQ)
            ? *(const float4*)(xq + ((size_t)(n * SEQ_LEN + s) * HEAD_DIM) + c * 4)
            : *(const float4*)(xk + ((size_t)s * HEAD_DIM) + c * 4);
        xs2[n][c * 4 + 0] = make_float2(v.x, v.x);
        xs2[n][c * 4 + 1] = make_float2(v.y, v.y);
        xs2[n][c * 4 + 2] = make_float2(v.z, v.z);
        xs2[n][c * 4 + 3] = make_float2(v.w, v.w);
    }
    __syncthreads();

    // ---- Accumulate: 8 h-steps x 9 rows, packed f32x2 ----
    unsigned long long acc01[NROWS], acc23[NROWS];
    #pragma unroll
    for (int n = 0; n < NROWS; n++) { acc01[n] = 0ull; acc23[n] = 0ull; }

    #pragma unroll
    for (int h = 0; h < HCHUNK; h++) {
        const int hh = g * HCHUNK + h;
        unsigned long long r01, r23;
        asm("mov.b64 %0, {%1, %2};" : "=l"(r01) : "f"(rv[h].x), "f"(rv[h].y));
        asm("mov.b64 %0, {%1, %2};" : "=l"(r23) : "f"(rv[h].z), "f"(rv[h].w));
        #pragma unroll
        for (int n = 0; n < NROWS; n++) {
            const unsigned long long x2 =
                *(const unsigned long long*)&xs2[n][hh];   // LDS.64 broadcast
            asm("fma.rn.f32x2 %0, %1, %2, %0;" : "+l"(acc01[n]) : "l"(x2), "l"(r01));
            asm("fma.rn.f32x2 %0, %1, %2, %0;" : "+l"(acc23[n]) : "l"(x2), "l"(r23));
        }
    }

    // ---- Write partials (STS.128) ----
    #pragma unroll
    for (int n = 0; n < NROWS; n++) {
        float a0, a1, a2, a3;
        asm("mov.b64 {%0, %1}, %2;" : "=f"(a0), "=f"(a1) : "l"(acc01[n]));
        asm("mov.b64 {%0, %1}, %2;" : "=f"(a2), "=f"(a3) : "l"(acc23[n]));
        *(float4*)&part[g][n][t * 4] = make_float4(a0, a1, a2, a3);
    }
    __syncthreads();

    // ---- Reduce 16 partials: 9 rows x 16 float4-chunks = 144 outputs ----
    // n=8 lands exactly at the xk output block (uniform indexing).
    if (tid < NROWS * (DTILE / 4)) {
        const int n = tid / (DTILE / 4);
        const int c = tid % (DTILE / 4);
        float4 v = make_float4(0.f, 0.f, 0.f, 0.f);
        #pragma unroll
        for (int gg = 0; gg < NGROUPS; gg++) {
            const float4 p = *(const float4*)&part[gg][n][c * 4];
            v.x += p.x; v.y += p.y; v.z += p.z; v.w += p.w;
        }
        const size_t o = (size_t)(n * SEQ_LEN + s) * HEAD_DIM + dh * DTILE + c * 4;
        *(float4*)(out + o) = v;
    }
}

extern "C" void kernel_launch(void* const* d_in, const int* in_sizes, int n_in,
                              void* d_out, int out_size) {
    const float* xq  = (const float*)d_in[0];
    const float* xk  = (const float*)d_in[1];
    const float* rot = (const float*)d_in[2];
    float* out = (float*)d_out;

    dim3 grid(SEQ_LEN, 2);
    rotary_kernel<<<grid, NTHREADS>>>(xq, xk, rot, out);
}